// round 10
// baseline (speedup 1.0000x reference)
#include <cuda_runtime.h>
#include <cuda_fp16.h>
#include <mma.h>
#include <math.h>
#include <cstdint>

using namespace nvcuda;

// Problem constants
#define BB 2
#define LL 2048
#define DD 1024
#define NQH 8
#define NKVH 2
#define HD 128
#define FFND 4096
#define ROWS (BB*LL)            // 4096
#define EPSV 1.1920929e-07f

// ---------------- scratch (device globals; no allocs allowed) ----------------
__device__ half  g_h  [ROWS*DD];        // rmsnorm1 out (fp16)
__device__ half  g_q  [ROWS*NQH*HD];    // q proj (fp16, pre-rope)
__device__ half  g_k  [ROWS*NKVH*HD];   // k proj (fp16, pre-rope)
__device__ half  g_v  [ROWS*NKVH*HD];   // v proj (fp16)
__device__ half  g_ctx[ROWS*DD];        // attention out (fp16)
__device__ float g_x1 [ROWS*DD];        // post-attn residual (fp32)
__device__ half  g_h2 [ROWS*DD];        // rmsnorm2 out (fp16)
__device__ half  g_g  [ROWS*FFND];      // gate (fp16)
__device__ half  g_u  [ROWS*FFND];      // up (fp16)
__device__ half  g_act[ROWS*FFND];      // silu*u (fp16)
// fp16 weight copies
__device__ half  g_wqh[DD*NQH*HD];
__device__ half  g_wkh[DD*NKVH*HD];
__device__ half  g_wvh[DD*NKVH*HD];
__device__ half  g_woh[DD*DD];
__device__ half  g_wgh[DD*FFND];
__device__ half  g_wuh[DD*FFND];
__device__ half  g_wdh[FFND*DD];
// rope tables (fp32)
__device__ float g_rsin[LL*64];
__device__ float g_rcos[LL*64];

// ---------------- pack helpers ----------------
union HPack { half2 h[2]; uint2 u; };
__device__ __forceinline__ uint2 pack4(float a, float b, float c, float d) {
    HPack p;
    p.h[0] = __floats2half2_rn(a, b);
    p.h[1] = __floats2half2_rn(c, d);
    return p.u;
}
union HPack8 { half2 h[4]; uint4 u; };

// ---------------- fused weight conversion + rope table (one launch) ----------------
#define N4_WQ 262144
#define N4_WK 65536
#define N4_WV 65536
#define N4_WO 262144
#define N4_WG 1048576
#define N4_WU 1048576
#define N4_WD 1048576
#define N4_TOT (N4_WQ+N4_WK+N4_WV+N4_WO+N4_WG+N4_WU+N4_WD)   // 3801088
#define NROPE (LL*64)                                         // 131072
#define NCONV (N4_TOT + NROPE)

__global__ void convert_weights_kernel(
    const float* __restrict__ wq, const float* __restrict__ wk, const float* __restrict__ wv,
    const float* __restrict__ wo, const float* __restrict__ wg, const float* __restrict__ wu,
    const float* __restrict__ wd,
    half* __restrict__ wqh, half* __restrict__ wkh, half* __restrict__ wvh,
    half* __restrict__ woh, half* __restrict__ wgh, half* __restrict__ wuh,
    half* __restrict__ wdh, float* __restrict__ rsin, float* __restrict__ rcos)
{
    int i = blockIdx.x * blockDim.x + threadIdx.x;
    if (i >= NCONV) return;
    if (i >= N4_TOT) {
        int j = i - N4_TOT;
        int pos = j >> 6, d = j & 63;
        float freq = powf(10000.0f, (float)d * (2.0f / HD));
        float rad = (float)pos / freq;
        float sn, cs;
        sincosf(rad, &sn, &cs);
        rsin[j] = sn;
        rcos[j] = cs;
        return;
    }
    const float* src; half* dst; int off = i;
    if      (off < N4_WQ)                         { src = wq; dst = wqh; }
    else if ((off -= N4_WQ) < N4_WK)              { src = wk; dst = wkh; }
    else if ((off -= N4_WK) < N4_WV)              { src = wv; dst = wvh; }
    else if ((off -= N4_WV) < N4_WO)              { src = wo; dst = woh; }
    else if ((off -= N4_WO) < N4_WG)              { src = wg; dst = wgh; }
    else if ((off -= N4_WG) < N4_WU)              { src = wu; dst = wuh; }
    else    { off -= N4_WU;                         src = wd; dst = wdh; }
    float4 v = ((const float4*)src)[off];
    ((uint2*)dst)[off] = pack4(v.x, v.y, v.z, v.w);
}

// ---------------- RMSNorm (fp32 in, fp16 out) ----------------
__global__ __launch_bounds__(256) void rmsnorm_kernel(
    const float* __restrict__ x, const float* __restrict__ w, half* __restrict__ out)
{
    int row = blockIdx.x;
    const float4* xr = (const float4*)(x + (size_t)row * DD);
    float4 v = xr[threadIdx.x];
    float s = v.x*v.x + v.y*v.y + v.z*v.z + v.w*v.w;
    #pragma unroll
    for (int off = 16; off; off >>= 1) s += __shfl_xor_sync(0xffffffffu, s, off);
    __shared__ float red[8];
    if ((threadIdx.x & 31) == 0) red[threadIdx.x >> 5] = s;
    __syncthreads();
    float tot = red[0]+red[1]+red[2]+red[3]+red[4]+red[5]+red[6]+red[7];
    float r = rsqrtf(tot * (1.0f/DD) + EPSV);
    const float4 wv = ((const float4*)w)[threadIdx.x];
    ((uint2*)(out + (size_t)row * DD))[threadIdx.x] =
        pack4(v.x*r*wv.x, v.y*r*wv.y, v.z*r*wv.z, v.w*r*wv.w);
}

// ---------------- fp16 tensor-core GEMM core ----------------
// Block tile 128x128x64, 2-stage cp.async, 4 warps (64x64 warp tile), 3 CTAs/SM
#define APH 72                  // A pitch (halves)
#define BPH 136                 // B pitch (halves)
#define HASZ (128*APH)          // 9216 halves
#define HBSZ (64*BPH)           // 8704 halves
#define HSTG (HASZ + HBSZ)      // 17920 halves per stage
#define GEMM_SMEM (2*HSTG*2)    // 71680 bytes

__device__ __forceinline__ void cp_async16h(half* smem, const half* g)
{
    unsigned int s = (unsigned int)__cvta_generic_to_shared(smem);
    asm volatile("cp.async.cg.shared.global [%0], [%1], 16;\n" :: "r"(s), "l"(g));
}

__device__ __forceinline__ void gemm_stage_load(
    half* As, half* Bs, const half* A, const half* B,
    int K, int ldb, int bm0, int col0, int k0, int tid)
{
    #pragma unroll
    for (int p = 0; p < 8; p++) {
        int idx = p * 128 + tid;
        int row = idx >> 3, c8 = (idx & 7) * 8;
        cp_async16h(As + row*APH + c8, A + (size_t)(bm0 + row)*K + k0 + c8);
    }
    #pragma unroll
    for (int p = 0; p < 8; p++) {
        int idx = p * 128 + tid;
        int br = idx >> 4, bc8 = (idx & 15) * 8;
        cp_async16h(Bs + br*BPH + bc8, B + (size_t)(k0 + br)*ldb + col0 + bc8);
    }
    asm volatile("cp.async.commit_group;\n" ::);
}

template <typename OT>
__device__ __forceinline__ void gemm_core(
    const half* __restrict__ A, const half* __restrict__ B,
    const float* __restrict__ Res, OT* __restrict__ C,
    int K, int ldb, int ldc, int bm0, int col0)
{
    extern __shared__ half smh[];
    int tid  = threadIdx.x;
    int warp = tid >> 5;
    int wm = warp & 1;
    int wn = warp >> 1;

    wmma::fragment<wmma::accumulator, 16,16,16, float> acc[4][4];
    #pragma unroll
    for (int i = 0; i < 4; i++)
        #pragma unroll
        for (int j = 0; j < 4; j++)
            wmma::fill_fragment(acc[i][j], 0.0f);

    int nk = K >> 6;

    gemm_stage_load(smh, smh + HASZ, A, B, K, ldb, bm0, col0, 0, tid);

    for (int kt = 0; kt < nk; kt++) {
        asm volatile("cp.async.wait_group 0;\n" ::);
        __syncthreads();

        if (kt + 1 < nk) {
            int s = (kt + 1) & 1;
            gemm_stage_load(smh + s*HSTG, smh + s*HSTG + HASZ, A, B, K, ldb, bm0, col0, (kt + 1) << 6, tid);
        }

        half* As = smh + (kt & 1) * HSTG;
        half* Bs = As + HASZ;
        #pragma unroll
        for (int ks = 0; ks < 4; ks++) {
            wmma::fragment<wmma::matrix_a, 16,16,16, half, wmma::row_major> af[4];
            wmma::fragment<wmma::matrix_b, 16,16,16, half, wmma::row_major> bf[4];
            #pragma unroll
            for (int i = 0; i < 4; i++)
                wmma::load_matrix_sync(af[i], As + (wm*64 + i*16)*APH + ks*16, APH);
            #pragma unroll
            for (int j = 0; j < 4; j++)
                wmma::load_matrix_sync(bf[j], Bs + (ks*16)*BPH + wn*64 + j*16, BPH);
            #pragma unroll
            for (int i = 0; i < 4; i++)
                #pragma unroll
                for (int j = 0; j < 4; j++)
                    wmma::mma_sync(acc[i][j], af[i], bf[j], acc[i][j]);
        }
    }

    if constexpr (sizeof(OT) == 4) {
        #pragma unroll
        for (int i = 0; i < 4; i++) {
            int r0 = bm0 + wm*64 + i*16;
            #pragma unroll
            for (int j = 0; j < 4; j++) {
                int c0 = col0 + wn*64 + j*16;
                if (Res) {
                    wmma::fragment<wmma::accumulator, 16,16,16, float> rf;
                    wmma::load_matrix_sync(rf, Res + (size_t)r0*ldc + c0, ldc, wmma::mem_row_major);
                    #pragma unroll
                    for (int e = 0; e < rf.num_elements; e++)
                        acc[i][j].x[e] += rf.x[e];
                }
                wmma::store_matrix_sync((float*)C + (size_t)r0*ldc + c0, acc[i][j], ldc, wmma::mem_row_major);
            }
        }
    } else {
        // fp16 output: stage via smem, convert, coalesced uint4 stores
        __syncthreads();
        float* scratch = (float*)smh;            // 4 warps * 4096 floats = 64 KB
        #pragma unroll
        for (int i = 0; i < 4; i++)
            #pragma unroll
            for (int j = 0; j < 4; j++)
                wmma::store_matrix_sync(scratch + warp*4096 + (i*16)*64 + j*16,
                                        acc[i][j], 64, wmma::mem_row_major);
        __syncthreads();
        #pragma unroll
        for (int it = 0; it < 16; it++) {
            int idx = it * 128 + tid;
            int row = idx >> 4, c8 = (idx & 15) * 8;
            int wid = (row >> 6) + ((c8 >> 6) << 1);
            const float* src = scratch + wid*4096 + (row & 63)*64 + (c8 & 63);
            HPack8 p;
            #pragma unroll
            for (int e = 0; e < 4; e++)
                p.h[e] = __floats2half2_rn(src[e*2], src[e*2+1]);
            *(uint4*)((half*)C + (size_t)(bm0 + row)*ldc + col0 + c8) = p.u;
        }
    }
}

__global__ __launch_bounds__(128, 3) void gemm_kernel(
    const half* __restrict__ A, const half* __restrict__ B,
    const float* __restrict__ Res, float* __restrict__ C, int K, int N)
{
    gemm_core<float>(A, B, Res, C, K, N, N, blockIdx.y * 128, blockIdx.x * 128);
}

__global__ __launch_bounds__(128, 3) void qkv_kernel(
    const half* __restrict__ h,
    const half* __restrict__ wq, const half* __restrict__ wk, const half* __restrict__ wv,
    half* __restrict__ q, half* __restrict__ k, half* __restrict__ v)
{
    int bn = blockIdx.x;
    const half* B; half* C; int ldn; int c0;
    if (bn < 8)       { B = wq; C = q; ldn = NQH*HD;  c0 = bn * 128; }
    else if (bn < 10) { B = wk; C = k; ldn = NKVH*HD; c0 = (bn - 8) * 128; }
    else              { B = wv; C = v; ldn = NKVH*HD; c0 = (bn - 10) * 128; }
    gemm_core<half>(h, B, nullptr, C, DD, ldn, ldn, blockIdx.y * 128, c0);
}

__global__ __launch_bounds__(128, 3) void gu_kernel(
    const half* __restrict__ h2,
    const half* __restrict__ wg, const half* __restrict__ wu,
    half* __restrict__ g, half* __restrict__ u)
{
    int bn = blockIdx.x;
    const half* B = (bn < 32) ? wg : wu;
    half* C       = (bn < 32) ? g  : u;
    int c0 = (bn & 31) * 128;
    gemm_core<half>(h2, B, nullptr, C, DD, FFND, FFND, blockIdx.y * 128, c0);
}

// ---------------- Flash attention: fp16 in/out, fused rope, fp32 softmax ----------------
#define TQ 64
#define TK 64
#define HP 136
#define SP 72
#define PP 80
#define OP 132
#define ATTN_SMEM (3*TQ*HP*2 + TQ*SP*4 + TQ*PP*2 + TQ*OP*4)   // 114688 bytes

__global__ __launch_bounds__(256, 2) void attn_kernel(
    const half* __restrict__ Q, const half* __restrict__ K,
    const half* __restrict__ V, half* __restrict__ O,
    const float* __restrict__ rsin, const float* __restrict__ rcos)
{
    extern __shared__ char smraw[];
    half*  hQ = (half*)smraw;
    half*  hK = hQ + TQ * HP;
    half*  hV = hK + TQ * HP;
    float* sS = (float*)(hV + TQ * HP);
    half*  sP = (half*)(sS + TQ * SP);
    float* sO = (float*)(sP + TQ * PP);

    int qt = (gridDim.x - 1) - blockIdx.x;
    int h = blockIdx.y, b = blockIdx.z;
    int kh = h >> 2;
    int tid = threadIdx.x;
    int warp = tid >> 5, lane = tid & 31;
    int q0 = qt * TQ;
    int wr = warp & 1, wc = warp >> 1;

    // load Q tile with fused rope (pairs: col c8 and c8+64, c8 in [0,64))
    #pragma unroll
    for (int it = 0; it < 2; it++) {
        int idx = it * 256 + tid;
        int r = idx >> 3, c8 = (idx & 7) * 8;
        const half* qp = Q + ((size_t)((b*LL + q0 + r)*NQH + h))*HD;
        HPack8 a, bb;
        a.u  = *(const uint4*)(qp + c8);
        bb.u = *(const uint4*)(qp + c8 + 64);
        int pos = q0 + r;
        const float* sp = rsin + pos*64 + c8;
        const float* cp = rcos + pos*64 + c8;
        HPack8 oa, ob;
        #pragma unroll
        for (int e = 0; e < 4; e++) {
            float2 x1 = __half22float2(a.h[e]);
            float2 x2 = __half22float2(bb.h[e]);
            float s0 = sp[e*2], s1 = sp[e*2+1];
            float c0 = cp[e*2], c1 = cp[e*2+1];
            oa.h[e] = __floats2half2_rn(x1.x*c0 - x2.x*s0, x1.y*c1 - x2.y*s1);
            ob.h[e] = __floats2half2_rn(x2.x*c0 + x1.x*s0, x2.y*c1 + x1.y*s1);
        }
        *(uint4*)(hQ + r * HP + c8)      = oa.u;
        *(uint4*)(hQ + r * HP + c8 + 64) = ob.u;
    }

    float o[8][4], m[8], l[8];
    #pragma unroll
    for (int r = 0; r < 8; r++) {
        m[r] = -1e30f; l[r] = 0.f;
        o[r][0] = o[r][1] = o[r][2] = o[r][3] = 0.f;
    }
    const float scale = 0.08838834764831845f;

    for (int kt = 0; kt <= qt; kt++) {
        int kb = kt * TK;
        // K tile with fused rope
        #pragma unroll
        for (int it = 0; it < 2; it++) {
            int idx = it * 256 + tid;
            int j = idx >> 3, c8 = (idx & 7) * 8;
            const half* kp = K + ((size_t)((b*LL + kb + j)*NKVH + kh))*HD;
            HPack8 a, bb;
            a.u  = *(const uint4*)(kp + c8);
            bb.u = *(const uint4*)(kp + c8 + 64);
            int pos = kb + j;
            const float* sp = rsin + pos*64 + c8;
            const float* cp = rcos + pos*64 + c8;
            HPack8 oa, ob;
            #pragma unroll
            for (int e = 0; e < 4; e++) {
                float2 x1 = __half22float2(a.h[e]);
                float2 x2 = __half22float2(bb.h[e]);
                float s0 = sp[e*2], s1 = sp[e*2+1];
                float c0 = cp[e*2], c1 = cp[e*2+1];
                oa.h[e] = __floats2half2_rn(x1.x*c0 - x2.x*s0, x1.y*c1 - x2.y*s1);
                ob.h[e] = __floats2half2_rn(x2.x*c0 + x1.x*s0, x2.y*c1 + x1.y*s1);
            }
            *(uint4*)(hK + j * HP + c8)      = oa.u;
            *(uint4*)(hK + j * HP + c8 + 64) = ob.u;
        }
        // V tile plain copy
        #pragma unroll
        for (int it = 0; it < 4; it++) {
            int idx = it * 256 + tid;
            int j = idx >> 4, c8 = (idx & 15) * 8;
            *(uint4*)(hV + j * HP + c8) =
                *(const uint4*)(V + ((size_t)((b*LL + kb + j)*NKVH + kh))*HD + c8);
        }
        __syncthreads();   // B

        // ---- S = Q @ K^T ----
        {
            wmma::fragment<wmma::accumulator, 16,16,16, float> sacc[2];
            wmma::fill_fragment(sacc[0], 0.0f);
            wmma::fill_fragment(sacc[1], 0.0f);
            #pragma unroll
            for (int kk = 0; kk < 8; kk++) {
                wmma::fragment<wmma::matrix_b, 16,16,16, half, wmma::col_major> bf;
                wmma::load_matrix_sync(bf, hK + (wc*16)*HP + kk*16, HP);
                #pragma unroll
                for (int i = 0; i < 2; i++) {
                    wmma::fragment<wmma::matrix_a, 16,16,16, half, wmma::row_major> af;
                    wmma::load_matrix_sync(af, hQ + (wr*32 + i*16)*HP + kk*16, HP);
                    wmma::mma_sync(sacc[i], af, bf, sacc[i]);
                }
            }
            wmma::store_matrix_sync(sS + (wr*32 +  0)*SP + wc*16, sacc[0], SP, wmma::mem_row_major);
            wmma::store_matrix_sync(sS + (wr*32 + 16)*SP + wc*16, sacc[1], SP, wmma::mem_row_major);
        }
        __syncthreads();   // C

        // ---- online softmax ----
        #pragma unroll
        for (int rr = 0; rr < 8; rr++) {
            int row = warp*8 + rr;
            int qi = q0 + row;
            float s1 = sS[row*SP + lane];
            float s2 = sS[row*SP + lane + 32];
            s1 = (kb + lane      <= qi) ? s1 * scale : -1e30f;
            s2 = (kb + lane + 32 <= qi) ? s2 * scale : -1e30f;
            float mx = fmaxf(s1, s2);
            #pragma unroll
            for (int off = 16; off; off >>= 1)
                mx = fmaxf(mx, __shfl_xor_sync(0xffffffffu, mx, off));
            float mnew = fmaxf(m[rr], mx);
            float p1 = __expf(s1 - mnew);
            float p2 = __expf(s2 - mnew);
            float ps = p1 + p2;
            #pragma unroll
            for (int off = 16; off; off >>= 1)
                ps += __shfl_xor_sync(0xffffffffu, ps, off);
            float alpha = __expf(m[rr] - mnew);
            m[rr] = mnew;
            l[rr] = l[rr] * alpha + ps;
            o[rr][0] *= alpha; o[rr][1] *= alpha; o[rr][2] *= alpha; o[rr][3] *= alpha;
            sP[row*PP + lane]      = __float2half(p1);
            sP[row*PP + lane + 32] = __float2half(p2);
        }
        __syncthreads();   // D

        // ---- PV ----
        {
            wmma::fragment<wmma::accumulator, 16,16,16, float> pacc[2][2];
            #pragma unroll
            for (int i = 0; i < 2; i++)
                #pragma unroll
                for (int j = 0; j < 2; j++)
                    wmma::fill_fragment(pacc[i][j], 0.0f);
            #pragma unroll
            for (int kk = 0; kk < 4; kk++) {
                wmma::fragment<wmma::matrix_a, 16,16,16, half, wmma::row_major> af[2];
                wmma::fragment<wmma::matrix_b, 16,16,16, half, wmma::row_major> bf[2];
                #pragma unroll
                for (int i = 0; i < 2; i++)
                    wmma::load_matrix_sync(af[i], sP + (wr*32 + i*16)*PP + kk*16, PP);
                #pragma unroll
                for (int j = 0; j < 2; j++)
                    wmma::load_matrix_sync(bf[j], hV + (kk*16)*HP + wc*32 + j*16, HP);
                #pragma unroll
                for (int i = 0; i < 2; i++)
                    #pragma unroll
                    for (int j = 0; j < 2; j++)
                        wmma::mma_sync(pacc[i][j], af[i], bf[j], pacc[i][j]);
            }
            #pragma unroll
            for (int i = 0; i < 2; i++)
                #pragma unroll
                for (int j = 0; j < 2; j++)
                    wmma::store_matrix_sync(sO + (wr*32 + i*16)*OP + wc*32 + j*16,
                                            pacc[i][j], OP, wmma::mem_row_major);
        }
        __syncthreads();   // E

        #pragma unroll
        for (int rr = 0; rr < 8; rr++) {
            int row = warp*8 + rr;
            float4 pv = *(const float4*)(sO + row*OP + lane*4);
            o[rr][0] += pv.x; o[rr][1] += pv.y; o[rr][2] += pv.z; o[rr][3] += pv.w;
        }
    }

    #pragma unroll
    for (int rr = 0; rr < 8; rr++) {
        int qi = q0 + warp*8 + rr;
        float inv = 1.0f / l[rr];
        *(uint2*)(O + ((size_t)((b*LL + qi)*NQH + h))*HD + lane*4) =
            pack4(o[rr][0]*inv, o[rr][1]*inv, o[rr][2]*inv, o[rr][3]*inv);
    }
}

// ---------------- silu(g) * u -> fp16 (fp16 in) ----------------
__global__ void silu_mul_kernel(const half* __restrict__ g, const half* __restrict__ u,
                                half* __restrict__ out, int n4)
{
    int i = blockIdx.x * blockDim.x + threadIdx.x;
    if (i >= n4) return;
    HPack gp, up;
    gp.u = ((const uint2*)g)[i];
    up.u = ((const uint2*)u)[i];
    float2 g0 = __half22float2(gp.h[0]), g1 = __half22float2(gp.h[1]);
    float2 u0 = __half22float2(up.h[0]), u1 = __half22float2(up.h[1]);
    ((uint2*)out)[i] = pack4(
        g0.x / (1.f + __expf(-g0.x)) * u0.x,
        g0.y / (1.f + __expf(-g0.y)) * u0.y,
        g1.x / (1.f + __expf(-g1.x)) * u1.x,
        g1.y / (1.f + __expf(-g1.y)) * u1.y);
}

// ---------------- launch ----------------
extern "C" void kernel_launch(void* const* d_in, const int* in_sizes, int n_in,
                              void* d_out, int out_size)
{
    const float* x   = (const float*)d_in[0];
    const float* ln1 = (const float*)d_in[1];
    const float* wq  = (const float*)d_in[2];
    const float* wk  = (const float*)d_in[3];
    const float* wv  = (const float*)d_in[4];
    const float* wo  = (const float*)d_in[5];
    const float* ln2 = (const float*)d_in[6];
    const float* wg  = (const float*)d_in[7];
    const float* wu  = (const float*)d_in[8];
    const float* wd  = (const float*)d_in[9];
    float* out = (float*)d_out;

    half *h, *q, *k, *v, *ctx, *h2, *g, *u, *act;
    float *x1, *rsin, *rcos;
    half *wqh, *wkh, *wvh, *woh, *wgh, *wuh, *wdh;
    cudaGetSymbolAddress((void**)&h,   g_h);
    cudaGetSymbolAddress((void**)&q,   g_q);
    cudaGetSymbolAddress((void**)&k,   g_k);
    cudaGetSymbolAddress((void**)&v,   g_v);
    cudaGetSymbolAddress((void**)&ctx, g_ctx);
    cudaGetSymbolAddress((void**)&x1,  g_x1);
    cudaGetSymbolAddress((void**)&h2,  g_h2);
    cudaGetSymbolAddress((void**)&g,   g_g);
    cudaGetSymbolAddress((void**)&u,   g_u);
    cudaGetSymbolAddress((void**)&act, g_act);
    cudaGetSymbolAddress((void**)&wqh, g_wqh);
    cudaGetSymbolAddress((void**)&wkh, g_wkh);
    cudaGetSymbolAddress((void**)&wvh, g_wvh);
    cudaGetSymbolAddress((void**)&woh, g_woh);
    cudaGetSymbolAddress((void**)&wgh, g_wgh);
    cudaGetSymbolAddress((void**)&wuh, g_wuh);
    cudaGetSymbolAddress((void**)&wdh, g_wdh);
    cudaGetSymbolAddress((void**)&rsin, g_rsin);
    cudaGetSymbolAddress((void**)&rcos, g_rcos);

    cudaFuncSetAttribute(attn_kernel, cudaFuncAttributeMaxDynamicSharedMemorySize, ATTN_SMEM);
    cudaFuncSetAttribute(gemm_kernel, cudaFuncAttributeMaxDynamicSharedMemorySize, GEMM_SMEM);
    cudaFuncSetAttribute(qkv_kernel,  cudaFuncAttributeMaxDynamicSharedMemorySize, GEMM_SMEM);
    cudaFuncSetAttribute(gu_kernel,   cudaFuncAttributeMaxDynamicSharedMemorySize, GEMM_SMEM);

    // 0) weights -> fp16 + rope tables
    convert_weights_kernel<<<(NCONV + 255) / 256, 256>>>(
        wq, wk, wv, wo, wg, wu, wd, wqh, wkh, wvh, woh, wgh, wuh, wdh, rsin, rcos);
    // 1) rmsnorm1 -> fp16
    rmsnorm_kernel<<<ROWS, 256>>>(x, ln1, h);
    // 2) fused qkv projections -> fp16 q,k,v (pre-rope)
    qkv_kernel<<<dim3(12, ROWS/128), 128, GEMM_SMEM>>>(h, wqh, wkh, wvh, q, k, v);
    // 3) attention (rope fused at Q/K load)  <- ncu captures launch index 3
    attn_kernel<<<dim3(LL / TQ, NQH, BB), 256, ATTN_SMEM>>>(q, k, v, ctx, rsin, rcos);
    // 4) output proj + residual -> fp32 x1
    gemm_kernel<<<dim3(DD/128, ROWS/128), 128, GEMM_SMEM>>>(ctx, woh, x, x1, DD, DD);
    // 5) rmsnorm2 -> fp16
    rmsnorm_kernel<<<ROWS, 256>>>(x1, ln2, h2);
    // 6) fused ffn gate+up -> fp16 g,u
    gu_kernel<<<dim3(64, ROWS/128), 128, GEMM_SMEM>>>(h2, wgh, wuh, g, u);
    // 7) silu*mul -> fp16 act
    {
        int n4 = ROWS * FFND / 4;
        silu_mul_kernel<<<(n4 + 255) / 256, 256>>>(g, u, act, n4);
    }
    // 8) down proj + residual -> out
    gemm_kernel<<<dim3(DD/128, ROWS/128), 128, GEMM_SMEM>>>(act, wdh, x1, out, FFND, DD);
}

// round 11
// speedup vs baseline: 1.1567x; 1.1567x over previous
#include <cuda_runtime.h>
#include <cuda_fp16.h>
#include <mma.h>
#include <math.h>
#include <cstdint>

using namespace nvcuda;

// Problem constants
#define BB 2
#define LL 2048
#define DD 1024
#define NQH 8
#define NKVH 2
#define HD 128
#define FFND 4096
#define ROWS (BB*LL)            // 4096
#define EPSV 1.1920929e-07f

// ---------------- scratch (device globals; no allocs allowed) ----------------
__device__ half  g_h  [ROWS*DD];        // rmsnorm1 out (fp16)
__device__ half  g_q  [ROWS*NQH*HD];    // q proj (fp16, roped in epilogue)
__device__ half  g_k  [ROWS*NKVH*HD];   // k proj (fp16, roped in epilogue)
__device__ half  g_v  [ROWS*NKVH*HD];   // v proj (fp16)
__device__ half  g_ctx[ROWS*DD];        // attention out (fp16)
__device__ float g_x1 [ROWS*DD];        // post-attn residual (fp32)
__device__ half  g_h2 [ROWS*DD];        // rmsnorm2 out (fp16)
__device__ half  g_g  [ROWS*FFND];      // gate (fp16)
__device__ half  g_u  [ROWS*FFND];      // up (fp16)
__device__ half  g_act[ROWS*FFND];      // silu*u (fp16)
// fp16 weight copies
__device__ half  g_wqh[DD*NQH*HD];
__device__ half  g_wkh[DD*NKVH*HD];
__device__ half  g_wvh[DD*NKVH*HD];
__device__ half  g_woh[DD*DD];
__device__ half  g_wgh[DD*FFND];
__device__ half  g_wuh[DD*FFND];
__device__ half  g_wdh[FFND*DD];
// rope tables (fp32)
__device__ float g_rsin[LL*64];
__device__ float g_rcos[LL*64];

// ---------------- pack helpers ----------------
union HPack { half2 h[2]; uint2 u; };
__device__ __forceinline__ uint2 pack4(float a, float b, float c, float d) {
    HPack p;
    p.h[0] = __floats2half2_rn(a, b);
    p.h[1] = __floats2half2_rn(c, d);
    return p.u;
}
union HPack8 { half2 h[4]; uint4 u; };

// ---------------- fused weight conversion + rope table (one launch) ----------------
#define N4_WQ 262144
#define N4_WK 65536
#define N4_WV 65536
#define N4_WO 262144
#define N4_WG 1048576
#define N4_WU 1048576
#define N4_WD 1048576
#define N4_TOT (N4_WQ+N4_WK+N4_WV+N4_WO+N4_WG+N4_WU+N4_WD)   // 3801088
#define NROPE (LL*64)                                         // 131072
#define NCONV (N4_TOT + NROPE)

__global__ void convert_weights_kernel(
    const float* __restrict__ wq, const float* __restrict__ wk, const float* __restrict__ wv,
    const float* __restrict__ wo, const float* __restrict__ wg, const float* __restrict__ wu,
    const float* __restrict__ wd,
    half* __restrict__ wqh, half* __restrict__ wkh, half* __restrict__ wvh,
    half* __restrict__ woh, half* __restrict__ wgh, half* __restrict__ wuh,
    half* __restrict__ wdh, float* __restrict__ rsin, float* __restrict__ rcos)
{
    int i = blockIdx.x * blockDim.x + threadIdx.x;
    if (i >= NCONV) return;
    if (i >= N4_TOT) {
        int j = i - N4_TOT;
        int pos = j >> 6, d = j & 63;
        float freq = powf(10000.0f, (float)d * (2.0f / HD));
        float rad = (float)pos / freq;
        float sn, cs;
        sincosf(rad, &sn, &cs);
        rsin[j] = sn;
        rcos[j] = cs;
        return;
    }
    const float* src; half* dst; int off = i;
    if      (off < N4_WQ)                         { src = wq; dst = wqh; }
    else if ((off -= N4_WQ) < N4_WK)              { src = wk; dst = wkh; }
    else if ((off -= N4_WK) < N4_WV)              { src = wv; dst = wvh; }
    else if ((off -= N4_WV) < N4_WO)              { src = wo; dst = woh; }
    else if ((off -= N4_WO) < N4_WG)              { src = wg; dst = wgh; }
    else if ((off -= N4_WG) < N4_WU)              { src = wu; dst = wuh; }
    else    { off -= N4_WU;                         src = wd; dst = wdh; }
    float4 v = ((const float4*)src)[off];
    ((uint2*)dst)[off] = pack4(v.x, v.y, v.z, v.w);
}

// ---------------- RMSNorm (fp32 in, fp16 out) ----------------
__global__ __launch_bounds__(256) void rmsnorm_kernel(
    const float* __restrict__ x, const float* __restrict__ w, half* __restrict__ out)
{
    int row = blockIdx.x;
    const float4* xr = (const float4*)(x + (size_t)row * DD);
    float4 v = xr[threadIdx.x];
    float s = v.x*v.x + v.y*v.y + v.z*v.z + v.w*v.w;
    #pragma unroll
    for (int off = 16; off; off >>= 1) s += __shfl_xor_sync(0xffffffffu, s, off);
    __shared__ float red[8];
    if ((threadIdx.x & 31) == 0) red[threadIdx.x >> 5] = s;
    __syncthreads();
    float tot = red[0]+red[1]+red[2]+red[3]+red[4]+red[5]+red[6]+red[7];
    float r = rsqrtf(tot * (1.0f/DD) + EPSV);
    const float4 wv = ((const float4*)w)[threadIdx.x];
    ((uint2*)(out + (size_t)row * DD))[threadIdx.x] =
        pack4(v.x*r*wv.x, v.y*r*wv.y, v.z*r*wv.z, v.w*r*wv.w);
}

// ---------------- fp16 tensor-core GEMM core ----------------
// Block tile 128x128x64, 2-stage cp.async, 4 warps (64x64 warp tile)
#define APH 72                  // A pitch (halves)
#define BPH 136                 // B pitch (halves)
#define HASZ (128*APH)          // 9216 halves
#define HBSZ (64*BPH)           // 8704 halves
#define HSTG (HASZ + HBSZ)      // 17920 halves per stage
#define GEMM_SMEM (2*HSTG*2)    // 71680 bytes

__device__ __forceinline__ void cp_async16h(half* smem, const half* g)
{
    unsigned int s = (unsigned int)__cvta_generic_to_shared(smem);
    asm volatile("cp.async.cg.shared.global [%0], [%1], 16;\n" :: "r"(s), "l"(g));
}

__device__ __forceinline__ void gemm_stage_load(
    half* As, half* Bs, const half* A, const half* B,
    int K, int ldb, int bm0, int col0, int k0, int tid)
{
    #pragma unroll
    for (int p = 0; p < 8; p++) {
        int idx = p * 128 + tid;
        int row = idx >> 3, c8 = (idx & 7) * 8;
        cp_async16h(As + row*APH + c8, A + (size_t)(bm0 + row)*K + k0 + c8);
    }
    #pragma unroll
    for (int p = 0; p < 8; p++) {
        int idx = p * 128 + tid;
        int br = idx >> 4, bc8 = (idx & 15) * 8;
        cp_async16h(Bs + br*BPH + bc8, B + (size_t)(k0 + br)*ldb + col0 + bc8);
    }
    asm volatile("cp.async.commit_group;\n" ::);
}

// rsin != nullptr (fp16 path only): apply rope to the output tile in the
// epilogue; rope pair partner is column c^64 within the 128-wide tile.
template <typename OT>
__device__ __forceinline__ void gemm_core(
    const half* __restrict__ A, const half* __restrict__ B,
    const float* __restrict__ Res, OT* __restrict__ C,
    int K, int ldb, int ldc, int bm0, int col0,
    const float* __restrict__ rsin, const float* __restrict__ rcos)
{
    extern __shared__ half smh[];
    int tid  = threadIdx.x;
    int warp = tid >> 5;
    int wm = warp & 1;
    int wn = warp >> 1;

    wmma::fragment<wmma::accumulator, 16,16,16, float> acc[4][4];
    #pragma unroll
    for (int i = 0; i < 4; i++)
        #pragma unroll
        for (int j = 0; j < 4; j++)
            wmma::fill_fragment(acc[i][j], 0.0f);

    int nk = K >> 6;

    gemm_stage_load(smh, smh + HASZ, A, B, K, ldb, bm0, col0, 0, tid);

    for (int kt = 0; kt < nk; kt++) {
        asm volatile("cp.async.wait_group 0;\n" ::);
        __syncthreads();

        if (kt + 1 < nk) {
            int s = (kt + 1) & 1;
            gemm_stage_load(smh + s*HSTG, smh + s*HSTG + HASZ, A, B, K, ldb, bm0, col0, (kt + 1) << 6, tid);
        }

        half* As = smh + (kt & 1) * HSTG;
        half* Bs = As + HASZ;
        #pragma unroll
        for (int ks = 0; ks < 4; ks++) {
            wmma::fragment<wmma::matrix_a, 16,16,16, half, wmma::row_major> af[4];
            wmma::fragment<wmma::matrix_b, 16,16,16, half, wmma::row_major> bf[4];
            #pragma unroll
            for (int i = 0; i < 4; i++)
                wmma::load_matrix_sync(af[i], As + (wm*64 + i*16)*APH + ks*16, APH);
            #pragma unroll
            for (int j = 0; j < 4; j++)
                wmma::load_matrix_sync(bf[j], Bs + (ks*16)*BPH + wn*64 + j*16, BPH);
            #pragma unroll
            for (int i = 0; i < 4; i++)
                #pragma unroll
                for (int j = 0; j < 4; j++)
                    wmma::mma_sync(acc[i][j], af[i], bf[j], acc[i][j]);
        }
    }

    if constexpr (sizeof(OT) == 4) {
        #pragma unroll
        for (int i = 0; i < 4; i++) {
            int r0 = bm0 + wm*64 + i*16;
            #pragma unroll
            for (int j = 0; j < 4; j++) {
                int c0 = col0 + wn*64 + j*16;
                if (Res) {
                    wmma::fragment<wmma::accumulator, 16,16,16, float> rf;
                    wmma::load_matrix_sync(rf, Res + (size_t)r0*ldc + c0, ldc, wmma::mem_row_major);
                    #pragma unroll
                    for (int e = 0; e < rf.num_elements; e++)
                        acc[i][j].x[e] += rf.x[e];
                }
                wmma::store_matrix_sync((float*)C + (size_t)r0*ldc + c0, acc[i][j], ldc, wmma::mem_row_major);
            }
        }
    } else {
        // fp16 output: stage via smem, (optional rope), convert, coalesced stores
        __syncthreads();
        float* scratch = (float*)smh;            // 4 warps * 4096 floats = 64 KB
        #pragma unroll
        for (int i = 0; i < 4; i++)
            #pragma unroll
            for (int j = 0; j < 4; j++)
                wmma::store_matrix_sync(scratch + warp*4096 + (i*16)*64 + j*16,
                                        acc[i][j], 64, wmma::mem_row_major);
        __syncthreads();
        #pragma unroll
        for (int it = 0; it < 16; it++) {
            int idx = it * 128 + tid;
            int row = idx >> 4, c8 = (idx & 15) * 8;
            int wid  = (row >> 6) + ((c8 >> 6) << 1);
            const float* src = scratch + wid*4096 + (row & 63)*64 + (c8 & 63);
            HPack8 p;
            if (rsin) {
                int cpart = c8 ^ 64;
                int widp = (row >> 6) + ((cpart >> 6) << 1);
                const float* par = scratch + widp*4096 + (row & 63)*64 + (c8 & 63);
                int pos = (bm0 + row) & (LL - 1);
                int d = c8 & 63;
                const float* sp = rsin + pos*64 + d;
                const float* cp = rcos + pos*64 + d;
                if (c8 < 64) {
                    #pragma unroll
                    for (int e = 0; e < 4; e++)
                        p.h[e] = __floats2half2_rn(src[e*2]   * cp[e*2]   - par[e*2]   * sp[e*2],
                                                   src[e*2+1] * cp[e*2+1] - par[e*2+1] * sp[e*2+1]);
                } else {
                    #pragma unroll
                    for (int e = 0; e < 4; e++)
                        p.h[e] = __floats2half2_rn(src[e*2]   * cp[e*2]   + par[e*2]   * sp[e*2],
                                                   src[e*2+1] * cp[e*2+1] + par[e*2+1] * sp[e*2+1]);
                }
            } else {
                #pragma unroll
                for (int e = 0; e < 4; e++)
                    p.h[e] = __floats2half2_rn(src[e*2], src[e*2+1]);
            }
            *(uint4*)((half*)C + (size_t)(bm0 + row)*ldc + col0 + c8) = p.u;
        }
    }
}

__global__ __launch_bounds__(128, 3) void gemm_kernel(
    const half* __restrict__ A, const half* __restrict__ B,
    const float* __restrict__ Res, float* __restrict__ C, int K, int N)
{
    gemm_core<float>(A, B, Res, C, K, N, N, blockIdx.y * 128, blockIdx.x * 128, nullptr, nullptr);
}

__global__ __launch_bounds__(128, 3) void qkv_kernel(
    const half* __restrict__ h,
    const half* __restrict__ wq, const half* __restrict__ wk, const half* __restrict__ wv,
    half* __restrict__ q, half* __restrict__ k, half* __restrict__ v,
    const float* __restrict__ rsin, const float* __restrict__ rcos)
{
    int bn = blockIdx.x;
    const half* B; half* C; int ldn; int c0; bool rope;
    if (bn < 8)       { B = wq; C = q; ldn = NQH*HD;  c0 = bn * 128;        rope = true;  }
    else if (bn < 10) { B = wk; C = k; ldn = NKVH*HD; c0 = (bn - 8) * 128;  rope = true;  }
    else              { B = wv; C = v; ldn = NKVH*HD; c0 = (bn - 10) * 128; rope = false; }
    gemm_core<half>(h, B, nullptr, C, DD, ldn, ldn, blockIdx.y * 128, c0,
                    rope ? rsin : nullptr, rcos);
}

__global__ __launch_bounds__(128, 3) void gu_kernel(
    const half* __restrict__ h2,
    const half* __restrict__ wg, const half* __restrict__ wu,
    half* __restrict__ g, half* __restrict__ u)
{
    int bn = blockIdx.x;
    const half* B = (bn < 32) ? wg : wu;
    half* C       = (bn < 32) ? g  : u;
    int c0 = (bn & 31) * 128;
    gemm_core<half>(h2, B, nullptr, C, DD, FFND, FFND, blockIdx.y * 128, c0, nullptr, nullptr);
}

// ---------------- Flash attention: fp16 in/out, O accumulator in fragments ----------------
#define TQ 64
#define TK 64
#define HP 136
#define SP 72
#define PP 80
// hQ/hK/hV(3*17408) + sS(18432) + sP(10240) + sAlpha(256) + sL(256)
#define ATTN_SMEM (3*TQ*HP*2 + TQ*SP*4 + TQ*PP*2 + 2*TQ*4)   // 81408 bytes

__global__ __launch_bounds__(256, 2) void attn_kernel(
    const half* __restrict__ Q, const half* __restrict__ K,
    const half* __restrict__ V, half* __restrict__ O)
{
    extern __shared__ char smraw[];
    half*  hQ = (half*)smraw;
    half*  hK = hQ + TQ * HP;
    half*  hV = hK + TQ * HP;
    float* sS = (float*)(hV + TQ * HP);
    half*  sP = (half*)(sS + TQ * SP);
    float* sAlpha = (float*)(sP + TQ * PP);
    float* sL = sAlpha + TQ;

    int qt = (gridDim.x - 1) - blockIdx.x;    // heavy tiles first
    int h = blockIdx.y, b = blockIdx.z;
    int kh = h >> 2;
    int tid = threadIdx.x;
    int warp = tid >> 5, lane = tid & 31;
    int q0 = qt * TQ;
    int wr = warp & 1, wc = warp >> 1;

    // load Q tile (fp16 straight copy)
    #pragma unroll
    for (int it = 0; it < 4; it++) {
        int idx = it * 256 + tid;
        int r = idx >> 4, c8 = (idx & 15) * 8;
        *(uint4*)(hQ + r * HP + c8) =
            *(const uint4*)(Q + ((size_t)((b*LL + q0 + r)*NQH + h))*HD + c8);
    }

    float m[8], l[8];
    #pragma unroll
    for (int r = 0; r < 8; r++) { m[r] = -1e30f; l[r] = 0.f; }

    // persistent PV accumulator fragments (64x64 rows/cols per warp-quadrant)
    wmma::fragment<wmma::accumulator, 16,16,16, float> pacc[2][2];
    #pragma unroll
    for (int i = 0; i < 2; i++)
        #pragma unroll
        for (int j = 0; j < 2; j++)
            wmma::fill_fragment(pacc[i][j], 0.0f);

    const float scale = 0.08838834764831845f;

    for (int kt = 0; kt <= qt; kt++) {
        int kb = kt * TK;
        #pragma unroll
        for (int it = 0; it < 4; it++) {
            int idx = it * 256 + tid;
            int j = idx >> 4, c8 = (idx & 15) * 8;
            *(uint4*)(hK + j * HP + c8) =
                *(const uint4*)(K + ((size_t)((b*LL + kb + j)*NKVH + kh))*HD + c8);
            *(uint4*)(hV + j * HP + c8) =
                *(const uint4*)(V + ((size_t)((b*LL + kb + j)*NKVH + kh))*HD + c8);
        }
        __syncthreads();   // B

        // ---- S = Q @ K^T ----
        {
            wmma::fragment<wmma::accumulator, 16,16,16, float> sacc[2];
            wmma::fill_fragment(sacc[0], 0.0f);
            wmma::fill_fragment(sacc[1], 0.0f);
            #pragma unroll
            for (int kk = 0; kk < 8; kk++) {
                wmma::fragment<wmma::matrix_b, 16,16,16, half, wmma::col_major> bf;
                wmma::load_matrix_sync(bf, hK + (wc*16)*HP + kk*16, HP);
                #pragma unroll
                for (int i = 0; i < 2; i++) {
                    wmma::fragment<wmma::matrix_a, 16,16,16, half, wmma::row_major> af;
                    wmma::load_matrix_sync(af, hQ + (wr*32 + i*16)*HP + kk*16, HP);
                    wmma::mma_sync(sacc[i], af, bf, sacc[i]);
                }
            }
            wmma::store_matrix_sync(sS + (wr*32 +  0)*SP + wc*16, sacc[0], SP, wmma::mem_row_major);
            wmma::store_matrix_sync(sS + (wr*32 + 16)*SP + wc*16, sacc[1], SP, wmma::mem_row_major);
        }
        __syncthreads();   // C

        // ---- online softmax (warp owns rows warp*8..+7) ----
        #pragma unroll
        for (int rr = 0; rr < 8; rr++) {
            int row = warp*8 + rr;
            int qi = q0 + row;
            float s1 = sS[row*SP + lane];
            float s2 = sS[row*SP + lane + 32];
            s1 = (kb + lane      <= qi) ? s1 * scale : -1e30f;
            s2 = (kb + lane + 32 <= qi) ? s2 * scale : -1e30f;
            float mx = fmaxf(s1, s2);
            #pragma unroll
            for (int off = 16; off; off >>= 1)
                mx = fmaxf(mx, __shfl_xor_sync(0xffffffffu, mx, off));
            float mnew = fmaxf(m[rr], mx);
            float p1 = __expf(s1 - mnew);
            float p2 = __expf(s2 - mnew);
            float ps = p1 + p2;
            #pragma unroll
            for (int off = 16; off; off >>= 1)
                ps += __shfl_xor_sync(0xffffffffu, ps, off);
            float alpha = __expf(m[rr] - mnew);
            m[rr] = mnew;
            l[rr] = l[rr] * alpha + ps;
            sP[row*PP + lane]      = __float2half(p1);
            sP[row*PP + lane + 32] = __float2half(p2);
            if (lane == 0) sAlpha[row] = alpha;
        }
        __syncthreads();   // D

        // ---- rescale pacc by alpha (per fragment row) then accumulate PV ----
        #pragma unroll
        for (int i = 0; i < 2; i++) {
            int rowA = wr*32 + i*16 + (lane >> 2);
            float aA = sAlpha[rowA];
            float aB = sAlpha[rowA + 8];
            #pragma unroll
            for (int j = 0; j < 2; j++) {
                pacc[i][j].x[0] *= aA; pacc[i][j].x[1] *= aA;
                pacc[i][j].x[2] *= aB; pacc[i][j].x[3] *= aB;
                pacc[i][j].x[4] *= aA; pacc[i][j].x[5] *= aA;
                pacc[i][j].x[6] *= aB; pacc[i][j].x[7] *= aB;
            }
        }
        #pragma unroll
        for (int kk = 0; kk < 4; kk++) {
            wmma::fragment<wmma::matrix_a, 16,16,16, half, wmma::row_major> af[2];
            wmma::fragment<wmma::matrix_b, 16,16,16, half, wmma::row_major> bf[2];
            #pragma unroll
            for (int i = 0; i < 2; i++)
                wmma::load_matrix_sync(af[i], sP + (wr*32 + i*16)*PP + kk*16, PP);
            #pragma unroll
            for (int j = 0; j < 2; j++)
                wmma::load_matrix_sync(bf[j], hV + (kk*16)*HP + wc*32 + j*16, HP);
            #pragma unroll
            for (int i = 0; i < 2; i++)
                #pragma unroll
                for (int j = 0; j < 2; j++)
                    wmma::mma_sync(pacc[i][j], af[i], bf[j], pacc[i][j]);
        }
        __syncthreads();   // E (protect hK/hV/sP/sAlpha reuse)
    }

    // publish l, then write O from fragments (normalize per row)
    #pragma unroll
    for (int rr = 0; rr < 8; rr++)
        if (lane == 0) sL[warp*8 + rr] = l[rr];
    __syncthreads();

    #pragma unroll
    for (int i = 0; i < 2; i++) {
        int rowA = wr*32 + i*16 + (lane >> 2);
        int rowB = rowA + 8;
        float invA = 1.0f / sL[rowA];
        float invB = 1.0f / sL[rowB];
        size_t baseA = ((size_t)((b*LL + q0 + rowA)*NQH + h))*HD;
        size_t baseB = ((size_t)((b*LL + q0 + rowB)*NQH + h))*HD;
        #pragma unroll
        for (int j = 0; j < 2; j++) {
            int c0 = wc*32 + j*16 + 2*(lane & 3);
            *(half2*)(O + baseA + c0)     = __floats2half2_rn(pacc[i][j].x[0]*invA, pacc[i][j].x[1]*invA);
            *(half2*)(O + baseB + c0)     = __floats2half2_rn(pacc[i][j].x[2]*invB, pacc[i][j].x[3]*invB);
            *(half2*)(O + baseA + c0 + 8) = __floats2half2_rn(pacc[i][j].x[4]*invA, pacc[i][j].x[5]*invA);
            *(half2*)(O + baseB + c0 + 8) = __floats2half2_rn(pacc[i][j].x[6]*invB, pacc[i][j].x[7]*invB);
        }
    }
}

// ---------------- silu(g) * u -> fp16 (fp16 in) ----------------
__global__ void silu_mul_kernel(const half* __restrict__ g, const half* __restrict__ u,
                                half* __restrict__ out, int n4)
{
    int i = blockIdx.x * blockDim.x + threadIdx.x;
    if (i >= n4) return;
    HPack gp, up;
    gp.u = ((const uint2*)g)[i];
    up.u = ((const uint2*)u)[i];
    float2 g0 = __half22float2(gp.h[0]), g1 = __half22float2(gp.h[1]);
    float2 u0 = __half22float2(up.h[0]), u1 = __half22float2(up.h[1]);
    ((uint2*)out)[i] = pack4(
        g0.x / (1.f + __expf(-g0.x)) * u0.x,
        g0.y / (1.f + __expf(-g0.y)) * u0.y,
        g1.x / (1.f + __expf(-g1.x)) * u1.x,
        g1.y / (1.f + __expf(-g1.y)) * u1.y);
}

// ---------------- launch ----------------
extern "C" void kernel_launch(void* const* d_in, const int* in_sizes, int n_in,
                              void* d_out, int out_size)
{
    const float* x   = (const float*)d_in[0];
    const float* ln1 = (const float*)d_in[1];
    const float* wq  = (const float*)d_in[2];
    const float* wk  = (const float*)d_in[3];
    const float* wv  = (const float*)d_in[4];
    const float* wo  = (const float*)d_in[5];
    const float* ln2 = (const float*)d_in[6];
    const float* wg  = (const float*)d_in[7];
    const float* wu  = (const float*)d_in[8];
    const float* wd  = (const float*)d_in[9];
    float* out = (float*)d_out;

    half *h, *q, *k, *v, *ctx, *h2, *g, *u, *act;
    float *x1, *rsin, *rcos;
    half *wqh, *wkh, *wvh, *woh, *wgh, *wuh, *wdh;
    cudaGetSymbolAddress((void**)&h,   g_h);
    cudaGetSymbolAddress((void**)&q,   g_q);
    cudaGetSymbolAddress((void**)&k,   g_k);
    cudaGetSymbolAddress((void**)&v,   g_v);
    cudaGetSymbolAddress((void**)&ctx, g_ctx);
    cudaGetSymbolAddress((void**)&x1,  g_x1);
    cudaGetSymbolAddress((void**)&h2,  g_h2);
    cudaGetSymbolAddress((void**)&g,   g_g);
    cudaGetSymbolAddress((void**)&u,   g_u);
    cudaGetSymbolAddress((void**)&act, g_act);
    cudaGetSymbolAddress((void**)&wqh, g_wqh);
    cudaGetSymbolAddress((void**)&wkh, g_wkh);
    cudaGetSymbolAddress((void**)&wvh, g_wvh);
    cudaGetSymbolAddress((void**)&woh, g_woh);
    cudaGetSymbolAddress((void**)&wgh, g_wgh);
    cudaGetSymbolAddress((void**)&wuh, g_wuh);
    cudaGetSymbolAddress((void**)&wdh, g_wdh);
    cudaGetSymbolAddress((void**)&rsin, g_rsin);
    cudaGetSymbolAddress((void**)&rcos, g_rcos);

    cudaFuncSetAttribute(attn_kernel, cudaFuncAttributeMaxDynamicSharedMemorySize, ATTN_SMEM);
    cudaFuncSetAttribute(gemm_kernel, cudaFuncAttributeMaxDynamicSharedMemorySize, GEMM_SMEM);
    cudaFuncSetAttribute(qkv_kernel,  cudaFuncAttributeMaxDynamicSharedMemorySize, GEMM_SMEM);
    cudaFuncSetAttribute(gu_kernel,   cudaFuncAttributeMaxDynamicSharedMemorySize, GEMM_SMEM);

    // 0) weights -> fp16 + rope tables
    convert_weights_kernel<<<(NCONV + 255) / 256, 256>>>(
        wq, wk, wv, wo, wg, wu, wd, wqh, wkh, wvh, woh, wgh, wuh, wdh, rsin, rcos);
    // 1) rmsnorm1 -> fp16
    rmsnorm_kernel<<<ROWS, 256>>>(x, ln1, h);
    // 2) fused qkv projections -> fp16 q,k,v (rope applied in epilogue)
    qkv_kernel<<<dim3(12, ROWS/128), 128, GEMM_SMEM>>>(h, wqh, wkh, wvh, q, k, v, rsin, rcos);
    // 3) attention -> fp16 ctx   <- ncu captures launch index 3
    attn_kernel<<<dim3(LL / TQ, NQH, BB), 256, ATTN_SMEM>>>(q, k, v, ctx);
    // 4) output proj + residual -> fp32 x1
    gemm_kernel<<<dim3(DD/128, ROWS/128), 128, GEMM_SMEM>>>(ctx, woh, x, x1, DD, DD);
    // 5) rmsnorm2 -> fp16
    rmsnorm_kernel<<<ROWS, 256>>>(x1, ln2, h2);
    // 6) fused ffn gate+up -> fp16 g,u
    gu_kernel<<<dim3(64, ROWS/128), 128, GEMM_SMEM>>>(h2, wgh, wuh, g, u);
    // 7) silu*mul -> fp16 act
    {
        int n4 = ROWS * FFND / 4;
        silu_mul_kernel<<<(n4 + 255) / 256, 256>>>(g, u, act, n4);
    }
    // 8) down proj + residual -> out
    gemm_kernel<<<dim3(DD/128, ROWS/128), 128, GEMM_SMEM>>>(act, wdh, x1, out, FFND, DD);
}